// round 13
// baseline (speedup 1.0000x reference)
#include <cuda_runtime.h>
#include <cuda_fp16.h>
#include <cstdint>

#define NN 100000
#define EE 1600000
#define SCAN_BLOCKS 391   // ceil(NN/256)

// Scratch (static device globals — no allocation in kernel_launch)
__device__ __half   g_xh[(size_t)NN * 128];   // fp16 in_feat
__device__ __half   g_hh[(size_t)NN * 128];   // fp16 h1 (layer-1 output)
__device__ __half   g_sh[(size_t)NN * 128];   // fp16 neigh buffer
__device__ __half   g_wcat[2][128 * 256];     // fp16 [Ws | Wn] per layer
__device__ int      g_cnt[NN];
__device__ unsigned long long g_state[SCAN_BLOCKS];
__device__ int      g_rowstart[NN + 1];
__device__ uint16_t g_rank[EE];               // within-dst rank of each edge
__device__ uint2    g_el2[EE];                // {src*32 (uint2-row idx), half2(w,w)}

// ---------------------------------------------------------------------------
// helpers
// ---------------------------------------------------------------------------
__device__ __forceinline__ __half2 u2h2(unsigned u) {
    return *reinterpret_cast<__half2*>(&u);
}

__device__ __forceinline__ void mma_fp16(float c[4],
                                         const unsigned a[4],
                                         const unsigned b[2]) {
    asm volatile(
        "mma.sync.aligned.m16n8k16.row.col.f32.f16.f16.f32 "
        "{%0,%1,%2,%3}, {%4,%5,%6,%7}, {%8,%9}, {%0,%1,%2,%3};"
        : "+f"(c[0]), "+f"(c[1]), "+f"(c[2]), "+f"(c[3])
        : "r"(a[0]), "r"(a[1]), "r"(a[2]), "r"(a[3]),
          "r"(b[0]), "r"(b[1]));
}

__device__ __forceinline__ void cp16(void* sdst, const void* gsrc, bool pred) {
    unsigned s = (unsigned)__cvta_generic_to_shared(sdst);
    int sz = pred ? 16 : 0;
    asm volatile("cp.async.cg.shared.global [%0], [%1], 16, %2;"
                 :: "r"(s), "l"(gsrc), "r"(sz));
}
__device__ __forceinline__ void cp_commit() {
    asm volatile("cp.async.commit_group;");
}
__device__ __forceinline__ void cp_wait0() {
    asm volatile("cp.async.wait_group 0;");
}

// ---------------------------------------------------------------------------
// prep + hist fused: fp16 feature copy, fp16 weight concat,
// dst histogram with per-edge rank capture. (g_cnt pre-zeroed by memset node)
// ---------------------------------------------------------------------------
__global__ void k_prephist(const float* __restrict__ x,
                           const int* __restrict__ dst,
                           const float* __restrict__ Ws1, const float* __restrict__ Wn1,
                           const float* __restrict__ Ws2, const float* __restrict__ Wn2) {
    int i = blockIdx.x * blockDim.x + threadIdx.x;

    if (i < NN * 32) {   // fp16 feature copy (one float4 -> 4 halves)
        float4 v = reinterpret_cast<const float4*>(x)[i];
        reinterpret_cast<__half2*>(g_xh)[i * 2]     = __floats2half2_rn(v.x, v.y);
        reinterpret_cast<__half2*>(g_xh)[i * 2 + 1] = __floats2half2_rn(v.z, v.w);
    }
    if (i < EE) {        // histogram + rank
        int r = atomicAdd(&g_cnt[dst[i]], 1);
        g_rank[i] = (uint16_t)r;
    }
    if (i < 65536) {     // weight concat
        int l   = i >> 15;
        int rem = i & 32767;     // f*256 + k
        int f   = rem >> 8;
        int k   = rem & 255;
        const float* W = l ? (k < 128 ? Ws2 : Wn2) : (k < 128 ? Ws1 : Wn1);
        g_wcat[l][rem] = __float2half_rn(W[f * 128 + (k & 127)]);
    }
}

// ---------------------------------------------------------------------------
// decoupled-lookback scan over g_cnt -> g_rowstart
// ---------------------------------------------------------------------------
__global__ void k_scan() {
    __shared__ int sm[256];
    __shared__ int s_prefix;
    const int b = blockIdx.x;
    const int t = threadIdx.x;
    const int i = b * 256 + t;

    int v = (i < NN) ? g_cnt[i] : 0;
    sm[t] = v;
    __syncthreads();
#pragma unroll
    for (int ofs = 1; ofs < 256; ofs <<= 1) {
        int tv = (t >= ofs) ? sm[t - ofs] : 0;
        __syncthreads();
        sm[t] += tv;
        __syncthreads();
    }
    int incl  = sm[t];
    int total = sm[255];

    if (t == 0) {
        if (b == 0) {
            atomicExch(&g_state[0], (2ULL << 32) | (unsigned)total);
            s_prefix = 0;
        } else {
            atomicExch(&g_state[b], (1ULL << 32) | (unsigned)total);
            int run = 0;
            for (int p = b - 1; p >= 0; p--) {
                unsigned long long s;
                do { s = atomicAdd(&g_state[p], 0ULL); } while ((s >> 32) == 0ULL);
                run += (int)(unsigned)s;
                if ((s >> 32) == 2ULL) break;
            }
            s_prefix = run;
            atomicExch(&g_state[b], (2ULL << 32) | (unsigned)(run + total));
        }
    }
    __syncthreads();

    if (i < NN) g_rowstart[i] = s_prefix + incl - v;
    if (i == 0) g_rowstart[NN] = EE;
}

// ---------------------------------------------------------------------------
// fill (atomic-free): pos = rowstart[dst] + rank; entries {src*32, half2(w,w)}
// ---------------------------------------------------------------------------
__global__ void k_fill(const int* __restrict__ src,
                       const int* __restrict__ dst,
                       const float* __restrict__ w) {
    int e = blockIdx.x * blockDim.x + threadIdx.x;
    if (e >= EE) return;
    int pos = g_rowstart[dst[e]] + (int)g_rank[e];
    __half2 w2 = __float2half2_rn(w[e]);
    g_el2[pos] = make_uint2((unsigned)src[e] * 32u,
                            *reinterpret_cast<unsigned*>(&w2));
}

// ---------------------------------------------------------------------------
// Gather-aggregate over fp16 features: one warp per dst node.
// Lane l owns 4 consecutive features (8 bytes). HFMA2 accumulation within
// each 4-edge group, flushed to fp32 between groups. Scalar tail in fp32.
// fp16 output (the store IS the rounding).
// ---------------------------------------------------------------------------
__global__ void k_gather(const __half* __restrict__ h,
                         __half* __restrict__ neigh) {
    const int n = (blockIdx.x * blockDim.x + threadIdx.x) >> 5;
    if (n >= NN) return;
    const int lane = threadIdx.x & 31;

    const int start = g_rowstart[n];
    const int end   = g_rowstart[n + 1];
    const uint2* h2 = reinterpret_cast<const uint2*>(h);  // 8B = 4 halves

    float a0 = 0.f, a1 = 0.f, a2 = 0.f, a3 = 0.f;
    const __half2 z2 = __float2half2_rn(0.f);

    int i = start;
    for (; i + 3 < end; i += 4) {
        uint2 e0 = g_el2[i];
        uint2 e1 = g_el2[i + 1];
        uint2 e2 = g_el2[i + 2];
        uint2 e3 = g_el2[i + 3];
        uint2 r0 = h2[(size_t)e0.x + lane];
        uint2 r1 = h2[(size_t)e1.x + lane];
        uint2 r2 = h2[(size_t)e2.x + lane];
        uint2 r3 = h2[(size_t)e3.x + lane];

        __half2 acc01 = z2, acc23 = z2;
        acc01 = __hfma2(u2h2(e0.y), u2h2(r0.x), acc01);
        acc23 = __hfma2(u2h2(e0.y), u2h2(r0.y), acc23);
        acc01 = __hfma2(u2h2(e1.y), u2h2(r1.x), acc01);
        acc23 = __hfma2(u2h2(e1.y), u2h2(r1.y), acc23);
        acc01 = __hfma2(u2h2(e2.y), u2h2(r2.x), acc01);
        acc23 = __hfma2(u2h2(e2.y), u2h2(r2.y), acc23);
        acc01 = __hfma2(u2h2(e3.y), u2h2(r3.x), acc01);
        acc23 = __hfma2(u2h2(e3.y), u2h2(r3.y), acc23);

        float2 f01 = __half22float2(acc01);
        float2 f23 = __half22float2(acc23);
        a0 += f01.x; a1 += f01.y;
        a2 += f23.x; a3 += f23.y;
    }
    for (; i < end; i++) {              // fp32 tail (full precision)
        uint2 e = g_el2[i];
        uint2 raw = h2[(size_t)e.x + lane];
        float w = __half2float(__low2half(u2h2(e.y)));
        float2 f0 = __half22float2(u2h2(raw.x));
        float2 f1 = __half22float2(u2h2(raw.y));
        a0 = fmaf(w, f0.x, a0);
        a1 = fmaf(w, f0.y, a1);
        a2 = fmaf(w, f1.x, a2);
        a3 = fmaf(w, f1.y, a3);
    }

    int deg = end - start;
    float inv = 1.0f / (float)max(deg, 1);
    __half2 r0 = __floats2half2_rn(a0 * inv, a1 * inv);
    __half2 r1 = __floats2half2_rn(a2 * inv, a3 * inv);
    uint2 packed;
    packed.x = *reinterpret_cast<unsigned*>(&r0);
    packed.y = *reinterpret_cast<unsigned*>(&r1);
    reinterpret_cast<uint2*>(neigh)[(size_t)n * 32 + lane] = packed;
}

// ---------------------------------------------------------------------------
// Fused SAGE GEMM, fp16 mma.sync.m16n8k16, fp32 accumulate. (as R9/R12)
// ---------------------------------------------------------------------------
#define SWZ(r, w) (((r) << 5) + ((w) ^ (((r) & 7) << 2)))

template <bool RELU, bool OUT_HALF>
__global__ void __launch_bounds__(256, 2)
k_gemm_fp16(const __half* __restrict__ X,
            const __half* __restrict__ S,
            const __half* __restrict__ Wcat,   // [128][256] fp16
            const float* __restrict__ bias,
            float* __restrict__ out,
            __half* __restrict__ outh) {
    __shared__ unsigned As[2][128 * 32];   // 16 KB each (words = half2)
    __shared__ unsigned Bs[128 * 32];      // 16 KB

    const int tid  = threadIdx.x;
    const int bm0  = blockIdx.x * 128;
    const int wid  = tid >> 5;
    const int lane = tid & 31;
    const int wm   = (wid & 1) * 64;
    const int wn   = (wid >> 1) * 32;
    const int gr   = lane >> 2;
    const int gc   = lane & 3;

    int rr[4], cc8[4];
#pragma unroll
    for (int l = 0; l < 4; l++) {
        int idx = l * 256 + tid;
        rr[l]  = idx >> 3;
        cc8[l] = idx & 7;
    }

    const uint4* wcat4 = reinterpret_cast<const uint4*>(Wcat);

    float acc[4][4][4];
#pragma unroll
    for (int mi = 0; mi < 4; mi++)
#pragma unroll
        for (int ni = 0; ni < 4; ni++)
#pragma unroll
            for (int c = 0; c < 4; c++) acc[mi][ni][c] = 0.f;

    auto issueA = [&](int c, int buf) {
        const __half* base = (c < 2) ? X : S;
        const int kb = (c & 1) * 64;
#pragma unroll
        for (int l = 0; l < 4; l++) {
            int grow = bm0 + rr[l];
            bool p = grow < NN;
            int gsafe = p ? grow : 0;
            const __half* gp = base + (size_t)gsafe * 128 + kb + cc8[l] * 8;
            cp16(&As[buf][SWZ(rr[l], cc8[l] * 4)], gp, p);
        }
        cp_commit();
    };

    uint4 breg[4];
    auto loadB = [&](int c) {
#pragma unroll
        for (int l = 0; l < 4; l++)
            breg[l] = wcat4[(size_t)rr[l] * 32 + c * 8 + cc8[l]];
    };

    issueA(0, 0);
    loadB(0);

#pragma unroll 1
    for (int c = 0; c < 4; c++) {
        cp_wait0();
        __syncthreads();

#pragma unroll
        for (int l = 0; l < 4; l++)
            *reinterpret_cast<uint4*>(&Bs[SWZ(rr[l], cc8[l] * 4)]) = breg[l];
        if (c < 3) {
            issueA(c + 1, (c + 1) & 1);
            loadB(c + 1);
        }

        __syncthreads();

        const unsigned* Ab = As[c & 1];
#pragma unroll
        for (int ks = 0; ks < 4; ks++) {
            const int w0 = ks * 8;

            unsigned a[4][4];
#pragma unroll
            for (int mi = 0; mi < 4; mi++) {
                int r = wm + mi * 16 + gr;
                a[mi][0] = Ab[SWZ(r,     w0 + gc)];
                a[mi][1] = Ab[SWZ(r + 8, w0 + gc)];
                a[mi][2] = Ab[SWZ(r,     w0 + gc + 4)];
                a[mi][3] = Ab[SWZ(r + 8, w0 + gc + 4)];
            }

            unsigned b[4][2];
#pragma unroll
            for (int ni = 0; ni < 4; ni++) {
                int n = wn + ni * 8 + gr;
                b[ni][0] = Bs[SWZ(n, w0 + gc)];
                b[ni][1] = Bs[SWZ(n, w0 + gc + 4)];
            }

#pragma unroll
            for (int mi = 0; mi < 4; mi++)
#pragma unroll
                for (int ni = 0; ni < 4; ni++)
                    mma_fp16(acc[mi][ni], a[mi], b[ni]);
        }
    }

#pragma unroll
    for (int ni = 0; ni < 4; ni++) {
        int col = wn + ni * 8 + gc * 2;
        float b0 = bias[col];
        float b1 = bias[col + 1];
#pragma unroll
        for (int mi = 0; mi < 4; mi++) {
            int r0 = bm0 + wm + mi * 16 + gr;
            float2 v0, v1;
            v0.x = acc[mi][ni][0] + b0;
            v0.y = acc[mi][ni][1] + b1;
            v1.x = acc[mi][ni][2] + b0;
            v1.y = acc[mi][ni][3] + b1;
            if (RELU) {
                v0.x = fmaxf(v0.x, 0.f); v0.y = fmaxf(v0.y, 0.f);
                v1.x = fmaxf(v1.x, 0.f); v1.y = fmaxf(v1.y, 0.f);
            }
            if (r0 < NN) {
                if (OUT_HALF)
                    *reinterpret_cast<__half2*>(&outh[(size_t)r0 * 128 + col]) =
                        __floats2half2_rn(v0.x, v0.y);
                else
                    *reinterpret_cast<float2*>(&out[(size_t)r0 * 128 + col]) = v0;
            }
            if (r0 + 8 < NN) {
                if (OUT_HALF)
                    *reinterpret_cast<__half2*>(&outh[(size_t)(r0 + 8) * 128 + col]) =
                        __floats2half2_rn(v1.x, v1.y);
                else
                    *reinterpret_cast<float2*>(&out[(size_t)(r0 + 8) * 128 + col]) = v1;
            }
        }
    }
}

// ---------------------------------------------------------------------------
// launch  (gather1 is kernel launch #4 -> ncu capture slot)
// ---------------------------------------------------------------------------
extern "C" void kernel_launch(void* const* d_in, const int* in_sizes, int n_in,
                              void* d_out, int out_size) {
    const float* in_feat = (const float*)d_in[0];
    const float* weights = (const float*)d_in[1];
    const int*   src     = (const int*)d_in[2];
    const int*   dst     = (const int*)d_in[3];
    const float* Ws1     = (const float*)d_in[4];
    const float* b1      = (const float*)d_in[5];
    const float* Wn1     = (const float*)d_in[6];
    const float* Ws2     = (const float*)d_in[7];
    const float* b2      = (const float*)d_in[8];
    const float* Wn2     = (const float*)d_in[9];
    float* out = (float*)d_out;

    void *p_xh, *p_hh, *p_sh, *p_w, *p_cnt, *p_state;
    cudaGetSymbolAddress(&p_xh, g_xh);
    cudaGetSymbolAddress(&p_hh, g_hh);
    cudaGetSymbolAddress(&p_sh, g_sh);
    cudaGetSymbolAddress(&p_w, g_wcat);
    cudaGetSymbolAddress(&p_cnt, g_cnt);
    cudaGetSymbolAddress(&p_state, g_state);
    __half* xh = (__half*)p_xh;
    __half* hh = (__half*)p_hh;
    __half* sh = (__half*)p_sh;
    __half* w0 = (__half*)p_w;
    __half* w1 = w0 + 128 * 256;

    const int eb = (EE + 255) / 256;
    const int big_blocks = (NN * 32 + 255) / 256;     // 12500
    const int gemm_blocks = (NN + 127) / 128;

    cudaMemsetAsync(p_cnt, 0, NN * sizeof(int), 0);
    cudaMemsetAsync(p_state, 0, SCAN_BLOCKS * sizeof(unsigned long long), 0);

    k_prephist<<<big_blocks, 256>>>(in_feat, dst, Ws1, Wn1, Ws2, Wn2);  // 1
    k_scan<<<SCAN_BLOCKS, 256>>>();                                     // 2
    k_fill<<<eb, 256>>>(src, dst, weights);                             // 3

    // Layer 1
    k_gather<<<big_blocks, 256>>>(xh, sh);                              // 4 (profiled)
    k_gemm_fp16<true, true><<<gemm_blocks, 256>>>(xh, sh, w0, b1, nullptr, hh);  // 5

    // Layer 2
    k_gather<<<big_blocks, 256>>>(hh, sh);                              // 6
    k_gemm_fp16<false, false><<<gemm_blocks, 256>>>(hh, sh, w1, b2, out, nullptr); // 7
}

// round 14
// speedup vs baseline: 1.1410x; 1.1410x over previous
#include <cuda_runtime.h>
#include <cuda_fp16.h>
#include <cstdint>

#define NN 100000
#define EE 1600000
#define SCAN_BLOCKS 391   // ceil(NN/256)
#define GEMM_TILES 782    // ceil(NN/128)
#define GEMM_CTAS 296     // 2 per SM
#define GEMM_SMEM (96 * 1024)

// Scratch (static device globals — no allocation in kernel_launch)
__device__ __half   g_xh[(size_t)NN * 128];   // fp16 in_feat
__device__ __half   g_hh[(size_t)NN * 128];   // fp16 h1 (layer-1 output)
__device__ __half   g_sh[(size_t)NN * 128];   // fp16 neigh buffer
__device__ __half   g_wcat[2][128 * 256];     // fp16 [Ws | Wn] per layer
__device__ int      g_cnt[NN];
__device__ unsigned long long g_state[SCAN_BLOCKS];
__device__ int      g_rowstart[NN + 1];
__device__ uint16_t g_rank[EE];               // within-dst rank of each edge
__device__ uint2    g_el2[EE];                // {src*32 (uint2-row idx), w bits}

// ---------------------------------------------------------------------------
// helpers
// ---------------------------------------------------------------------------
__device__ __forceinline__ void mma_fp16(float c[4],
                                         const unsigned a[4],
                                         const unsigned b[2]) {
    asm volatile(
        "mma.sync.aligned.m16n8k16.row.col.f32.f16.f16.f32 "
        "{%0,%1,%2,%3}, {%4,%5,%6,%7}, {%8,%9}, {%0,%1,%2,%3};"
        : "+f"(c[0]), "+f"(c[1]), "+f"(c[2]), "+f"(c[3])
        : "r"(a[0]), "r"(a[1]), "r"(a[2]), "r"(a[3]),
          "r"(b[0]), "r"(b[1]));
}

__device__ __forceinline__ void cp16(void* sdst, const void* gsrc, bool pred) {
    unsigned s = (unsigned)__cvta_generic_to_shared(sdst);
    int sz = pred ? 16 : 0;
    asm volatile("cp.async.cg.shared.global [%0], [%1], 16, %2;"
                 :: "r"(s), "l"(gsrc), "r"(sz));
}
__device__ __forceinline__ void cp_commit() {
    asm volatile("cp.async.commit_group;");
}
__device__ __forceinline__ void cp_wait0() {
    asm volatile("cp.async.wait_group 0;");
}

// ---------------------------------------------------------------------------
// prep + hist fused: fp16 feature copy, fp16 weight concat,
// dst histogram with per-edge rank capture. (g_cnt pre-zeroed by memset node)
// ---------------------------------------------------------------------------
__global__ void k_prephist(const float* __restrict__ x,
                           const int* __restrict__ dst,
                           const float* __restrict__ Ws1, const float* __restrict__ Wn1,
                           const float* __restrict__ Ws2, const float* __restrict__ Wn2) {
    int i = blockIdx.x * blockDim.x + threadIdx.x;

    if (i < NN * 32) {   // fp16 feature copy (one float4 -> 4 halves)
        float4 v = reinterpret_cast<const float4*>(x)[i];
        reinterpret_cast<__half2*>(g_xh)[i * 2]     = __floats2half2_rn(v.x, v.y);
        reinterpret_cast<__half2*>(g_xh)[i * 2 + 1] = __floats2half2_rn(v.z, v.w);
    }
    if (i < EE) {        // histogram + rank
        int r = atomicAdd(&g_cnt[dst[i]], 1);
        g_rank[i] = (uint16_t)r;
    }
    if (i < 65536) {     // weight concat
        int l   = i >> 15;
        int rem = i & 32767;     // f*256 + k
        int f   = rem >> 8;
        int k   = rem & 255;
        const float* W = l ? (k < 128 ? Ws2 : Wn2) : (k < 128 ? Ws1 : Wn1);
        g_wcat[l][rem] = __float2half_rn(W[f * 128 + (k & 127)]);
    }
}

// ---------------------------------------------------------------------------
// decoupled-lookback scan over g_cnt -> g_rowstart
// ---------------------------------------------------------------------------
__global__ void k_scan() {
    __shared__ int sm[256];
    __shared__ int s_prefix;
    const int b = blockIdx.x;
    const int t = threadIdx.x;
    const int i = b * 256 + t;

    int v = (i < NN) ? g_cnt[i] : 0;
    sm[t] = v;
    __syncthreads();
#pragma unroll
    for (int ofs = 1; ofs < 256; ofs <<= 1) {
        int tv = (t >= ofs) ? sm[t - ofs] : 0;
        __syncthreads();
        sm[t] += tv;
        __syncthreads();
    }
    int incl  = sm[t];
    int total = sm[255];

    if (t == 0) {
        if (b == 0) {
            atomicExch(&g_state[0], (2ULL << 32) | (unsigned)total);
            s_prefix = 0;
        } else {
            atomicExch(&g_state[b], (1ULL << 32) | (unsigned)total);
            int run = 0;
            for (int p = b - 1; p >= 0; p--) {
                unsigned long long s;
                do { s = atomicAdd(&g_state[p], 0ULL); } while ((s >> 32) == 0ULL);
                run += (int)(unsigned)s;
                if ((s >> 32) == 2ULL) break;
            }
            s_prefix = run;
            atomicExch(&g_state[b], (2ULL << 32) | (unsigned)(run + total));
        }
    }
    __syncthreads();

    if (i < NN) g_rowstart[i] = s_prefix + incl - v;
    if (i == 0) g_rowstart[NN] = EE;
}

// ---------------------------------------------------------------------------
// fill (atomic-free): pos = rowstart[dst] + rank; decode-free 8B entries
// ---------------------------------------------------------------------------
__global__ void k_fill(const int* __restrict__ src,
                       const int* __restrict__ dst,
                       const float* __restrict__ w) {
    int e = blockIdx.x * blockDim.x + threadIdx.x;
    if (e >= EE) return;
    int pos = g_rowstart[dst[e]] + (int)g_rank[e];
    g_el2[pos] = make_uint2((unsigned)src[e] * 32u, __float_as_uint(w[e]));
}

// ---------------------------------------------------------------------------
// Gather-aggregate over fp16 features (exact R12 shape — measured optimum):
// one warp per dst node, lane l owns 4 consecutive features (8 bytes),
// decode-free edge entries, straight 4x unroll, fp32 accumulation,
// fp16 output (the store IS the rounding).
// ---------------------------------------------------------------------------
__global__ void k_gather(const __half* __restrict__ h,
                         __half* __restrict__ neigh) {
    const int n = (blockIdx.x * blockDim.x + threadIdx.x) >> 5;
    if (n >= NN) return;
    const int lane = threadIdx.x & 31;

    const int start = g_rowstart[n];
    const int end   = g_rowstart[n + 1];
    const uint2* h2 = reinterpret_cast<const uint2*>(h);  // 8B = 4 halves

    float a0 = 0.f, a1 = 0.f, a2 = 0.f, a3 = 0.f;

    auto accum = [&](uint2 e) {
        float w = __uint_as_float(e.y);
        uint2 raw = h2[(size_t)e.x + lane];
        __half2 p0 = *reinterpret_cast<__half2*>(&raw.x);
        __half2 p1 = *reinterpret_cast<__half2*>(&raw.y);
        float2 f0 = __half22float2(p0);
        float2 f1 = __half22float2(p1);
        a0 = fmaf(w, f0.x, a0);
        a1 = fmaf(w, f0.y, a1);
        a2 = fmaf(w, f1.x, a2);
        a3 = fmaf(w, f1.y, a3);
    };

    int i = start;
    for (; i + 3 < end; i += 4) {
        uint2 e0 = g_el2[i];
        uint2 e1 = g_el2[i + 1];
        uint2 e2 = g_el2[i + 2];
        uint2 e3 = g_el2[i + 3];
        accum(e0); accum(e1); accum(e2); accum(e3);
    }
    for (; i < end; i++) accum(g_el2[i]);

    int deg = end - start;
    float inv = 1.0f / (float)max(deg, 1);
    __half2 r0 = __floats2half2_rn(a0 * inv, a1 * inv);
    __half2 r1 = __floats2half2_rn(a2 * inv, a3 * inv);
    uint2 packed;
    packed.x = *reinterpret_cast<unsigned*>(&r0);
    packed.y = *reinterpret_cast<unsigned*>(&r1);
    reinterpret_cast<uint2*>(neigh)[(size_t)n * 32 + lane] = packed;
}

// ---------------------------------------------------------------------------
// Persistent fused SAGE GEMM, fp16 mma.sync.m16n8k16, fp32 accumulate.
// 296 CTAs (2/SM) loop over 782 M-tiles. B (full 64 KB Wcat) staged into
// smem ONCE per CTA; A double-buffered via cp.async; ONE barrier per chunk
// (issueA(c+1) after sync(c) is safe: sync(c) => all warps done mma(c-1),
// the last reader of buffer (c+1)&1).
// Dyn smem: A 2x16KB | B 4x16KB = 96 KB.
// ---------------------------------------------------------------------------
#define SWZ(r, w) (((r) << 5) + ((w) ^ (((r) & 7) << 2)))

template <bool RELU, bool OUT_HALF>
__global__ void __launch_bounds__(256, 2)
k_gemm_fp16(const __half* __restrict__ X,
            const __half* __restrict__ S,
            const __half* __restrict__ Wcat,   // [128][256] fp16
            const float* __restrict__ bias,
            float* __restrict__ out,
            __half* __restrict__ outh) {
    extern __shared__ unsigned dsm[];
    unsigned* Asm = dsm;           // [2][4096] words
    unsigned* Bsm = dsm + 8192;    // [4][4096] words

    const int tid  = threadIdx.x;
    const int wid  = tid >> 5;
    const int lane = tid & 31;
    const int wm   = (wid & 1) * 64;
    const int wn   = (wid >> 1) * 32;
    const int gr   = lane >> 2;
    const int gc   = lane & 3;

    int rr[4], cc8[4];
#pragma unroll
    for (int l = 0; l < 4; l++) {
        int idx = l * 256 + tid;
        rr[l]  = idx >> 3;
        cc8[l] = idx & 7;
    }

    // --- stage ALL of B once (64 KB, 16 cp16 per thread)
#pragma unroll
    for (int c = 0; c < 4; c++) {
#pragma unroll
        for (int l = 0; l < 4; l++) {
            cp16(&Bsm[c * 4096 + SWZ(rr[l], cc8[l] * 4)],
                 Wcat + (size_t)rr[l] * 256 + c * 64 + cc8[l] * 8, true);
        }
    }
    cp_commit();
    cp_wait0();
    __syncthreads();

    auto issueA = [&](int c, int buf, int bm0) {
        const __half* base = (c < 2) ? X : S;
        const int kb = (c & 1) * 64;
#pragma unroll
        for (int l = 0; l < 4; l++) {
            int grow = bm0 + rr[l];
            bool p = grow < NN;
            int gsafe = p ? grow : 0;
            const __half* gp = base + (size_t)gsafe * 128 + kb + cc8[l] * 8;
            cp16(&Asm[buf * 4096 + SWZ(rr[l], cc8[l] * 4)], gp, p);
        }
        cp_commit();
    };

    for (int tile = blockIdx.x; tile < GEMM_TILES; tile += gridDim.x) {
        const int bm0 = tile * 128;

        float acc[4][4][4];
#pragma unroll
        for (int mi = 0; mi < 4; mi++)
#pragma unroll
            for (int ni = 0; ni < 4; ni++)
#pragma unroll
                for (int c = 0; c < 4; c++) acc[mi][ni][c] = 0.f;

        issueA(0, 0, bm0);

#pragma unroll 1
        for (int c = 0; c < 4; c++) {
            cp_wait0();
            __syncthreads();          // chunk c staged; all warps done mma(c-1)

            if (c < 3) issueA(c + 1, (c + 1) & 1, bm0);   // overlaps mma below

            const unsigned* Ab = &Asm[(c & 1) * 4096];
            const unsigned* Bb = &Bsm[c * 4096];
#pragma unroll
            for (int ks = 0; ks < 4; ks++) {
                const int w0 = ks * 8;

                unsigned a[4][4];
#pragma unroll
                for (int mi = 0; mi < 4; mi++) {
                    int r = wm + mi * 16 + gr;
                    a[mi][0] = Ab[SWZ(r,     w0 + gc)];
                    a[mi][1] = Ab[SWZ(r + 8, w0 + gc)];
                    a[mi][2] = Ab[SWZ(r,     w0 + gc + 4)];
                    a[mi][3] = Ab[SWZ(r + 8, w0 + gc + 4)];
                }

                unsigned b[4][2];
#pragma unroll
                for (int ni = 0; ni < 4; ni++) {
                    int n = wn + ni * 8 + gr;
                    b[ni][0] = Bb[SWZ(n, w0 + gc)];
                    b[ni][1] = Bb[SWZ(n, w0 + gc + 4)];
                }

#pragma unroll
                for (int mi = 0; mi < 4; mi++)
#pragma unroll
                    for (int ni = 0; ni < 4; ni++)
                        mma_fp16(acc[mi][ni], a[mi], b[ni]);
            }
        }

        // --- epilogue: +bias, optional relu; fp16 or fp32 stores
#pragma unroll
        for (int ni = 0; ni < 4; ni++) {
            int col = wn + ni * 8 + gc * 2;
            float b0 = bias[col];
            float b1 = bias[col + 1];
#pragma unroll
            for (int mi = 0; mi < 4; mi++) {
                int r0 = bm0 + wm + mi * 16 + gr;
                float2 v0, v1;
                v0.x = acc[mi][ni][0] + b0;
                v0.y = acc[mi][ni][1] + b1;
                v1.x = acc[mi][ni][2] + b0;
                v1.y = acc[mi][ni][3] + b1;
                if (RELU) {
                    v0.x = fmaxf(v0.x, 0.f); v0.y = fmaxf(v0.y, 0.f);
                    v1.x = fmaxf(v1.x, 0.f); v1.y = fmaxf(v1.y, 0.f);
                }
                if (r0 < NN) {
                    if (OUT_HALF)
                        *reinterpret_cast<__half2*>(&outh[(size_t)r0 * 128 + col]) =
                            __floats2half2_rn(v0.x, v0.y);
                    else
                        *reinterpret_cast<float2*>(&out[(size_t)r0 * 128 + col]) = v0;
                }
                if (r0 + 8 < NN) {
                    if (OUT_HALF)
                        *reinterpret_cast<__half2*>(&outh[(size_t)(r0 + 8) * 128 + col]) =
                            __floats2half2_rn(v1.x, v1.y);
                    else
                        *reinterpret_cast<float2*>(&out[(size_t)(r0 + 8) * 128 + col]) = v1;
                }
            }
        }
    }
}

// ---------------------------------------------------------------------------
// launch  (gather1 is kernel launch #4 -> ncu capture slot)
// ---------------------------------------------------------------------------
extern "C" void kernel_launch(void* const* d_in, const int* in_sizes, int n_in,
                              void* d_out, int out_size) {
    const float* in_feat = (const float*)d_in[0];
    const float* weights = (const float*)d_in[1];
    const int*   src     = (const int*)d_in[2];
    const int*   dst     = (const int*)d_in[3];
    const float* Ws1     = (const float*)d_in[4];
    const float* b1      = (const float*)d_in[5];
    const float* Wn1     = (const float*)d_in[6];
    const float* Ws2     = (const float*)d_in[7];
    const float* b2      = (const float*)d_in[8];
    const float* Wn2     = (const float*)d_in[9];
    float* out = (float*)d_out;

    void *p_xh, *p_hh, *p_sh, *p_w, *p_cnt, *p_state;
    cudaGetSymbolAddress(&p_xh, g_xh);
    cudaGetSymbolAddress(&p_hh, g_hh);
    cudaGetSymbolAddress(&p_sh, g_sh);
    cudaGetSymbolAddress(&p_w, g_wcat);
    cudaGetSymbolAddress(&p_cnt, g_cnt);
    cudaGetSymbolAddress(&p_state, g_state);
    __half* xh = (__half*)p_xh;
    __half* hh = (__half*)p_hh;
    __half* sh = (__half*)p_sh;
    __half* w0 = (__half*)p_w;
    __half* w1 = w0 + 128 * 256;

    cudaFuncSetAttribute(k_gemm_fp16<true, true>,
                         cudaFuncAttributeMaxDynamicSharedMemorySize, GEMM_SMEM);
    cudaFuncSetAttribute(k_gemm_fp16<false, false>,
                         cudaFuncAttributeMaxDynamicSharedMemorySize, GEMM_SMEM);

    const int eb = (EE + 255) / 256;
    const int big_blocks = (NN * 32 + 255) / 256;     // 12500

    cudaMemsetAsync(p_cnt, 0, NN * sizeof(int), 0);
    cudaMemsetAsync(p_state, 0, SCAN_BLOCKS * sizeof(unsigned long long), 0);

    k_prephist<<<big_blocks, 256>>>(in_feat, dst, Ws1, Wn1, Ws2, Wn2);  // 1
    k_scan<<<SCAN_BLOCKS, 256>>>();                                     // 2
    k_fill<<<eb, 256>>>(src, dst, weights);                             // 3

    // Layer 1
    k_gather<<<big_blocks, 256>>>(xh, sh);                              // 4 (profiled)
    k_gemm_fp16<true, true><<<GEMM_CTAS, 256, GEMM_SMEM>>>(             // 5
        xh, sh, w0, b1, nullptr, hh);

    // Layer 2
    k_gather<<<big_blocks, 256>>>(hh, sh);                              // 6
    k_gemm_fp16<false, false><<<GEMM_CTAS, 256, GEMM_SMEM>>>(           // 7
        hh, sh, w1, b2, out, nullptr);
}

// round 15
// speedup vs baseline: 1.1656x; 1.0216x over previous
#include <cuda_runtime.h>
#include <cuda_fp16.h>
#include <cstdint>

#define NN 100000
#define EE 1600000
#define SCAN_BLOCKS 391   // ceil(NN/256)
#define GEMM_TILES 782    // ceil(NN/128)
#define GEMM_CTAS 296     // 2 per SM
#define GEMM_SMEM (96 * 1024)

// Scratch (static device globals — zero-initialized at module load; kernels
// restore the zero state after use so every graph replay sees it zeroed)
__device__ __half   g_xh[(size_t)NN * 128];   // fp16 in_feat
__device__ __half   g_hh[(size_t)NN * 128];   // fp16 h1 (layer-1 output)
__device__ __half   g_sh[(size_t)NN * 128];   // fp16 neigh buffer
__device__ __half   g_wcat[2][128 * 256];     // fp16 [Ws | Wn] per layer
__device__ int      g_cnt[NN];                // re-zeroed by k_scan after read
__device__ unsigned long long g_state[SCAN_BLOCKS];  // zeroed by k_prephist
__device__ int      g_rowstart[NN + 1];
__device__ uint16_t g_rank[EE];               // within-dst rank of each edge
__device__ uint2    g_el2[EE];                // {src*32 (uint2-row idx), w bits}

// ---------------------------------------------------------------------------
// helpers
// ---------------------------------------------------------------------------
__device__ __forceinline__ void mma_fp16(float c[4],
                                         const unsigned a[4],
                                         const unsigned b[2]) {
    asm volatile(
        "mma.sync.aligned.m16n8k16.row.col.f32.f16.f16.f32 "
        "{%0,%1,%2,%3}, {%4,%5,%6,%7}, {%8,%9}, {%0,%1,%2,%3};"
        : "+f"(c[0]), "+f"(c[1]), "+f"(c[2]), "+f"(c[3])
        : "r"(a[0]), "r"(a[1]), "r"(a[2]), "r"(a[3]),
          "r"(b[0]), "r"(b[1]));
}

__device__ __forceinline__ void cp16(void* sdst, const void* gsrc, bool pred) {
    unsigned s = (unsigned)__cvta_generic_to_shared(sdst);
    int sz = pred ? 16 : 0;
    asm volatile("cp.async.cg.shared.global [%0], [%1], 16, %2;"
                 :: "r"(s), "l"(gsrc), "r"(sz));
}
__device__ __forceinline__ void cp_commit() {
    asm volatile("cp.async.commit_group;");
}
__device__ __forceinline__ void cp_wait0() {
    asm volatile("cp.async.wait_group 0;");
}

// ---------------------------------------------------------------------------
// prep + hist fused: fp16 feature copy, fp16 weight concat, scan-state zero,
// dst histogram with per-edge rank capture. (g_cnt is zero on entry: static
// init on first run, k_scan's post-read zeroing on later runs.)
// ---------------------------------------------------------------------------
__global__ void k_prephist(const float* __restrict__ x,
                           const int* __restrict__ dst,
                           const float* __restrict__ Ws1, const float* __restrict__ Wn1,
                           const float* __restrict__ Ws2, const float* __restrict__ Wn2) {
    int i = blockIdx.x * blockDim.x + threadIdx.x;

    if (i < NN * 32) {   // fp16 feature copy (one float4 -> 4 halves)
        float4 v = reinterpret_cast<const float4*>(x)[i];
        reinterpret_cast<__half2*>(g_xh)[i * 2]     = __floats2half2_rn(v.x, v.y);
        reinterpret_cast<__half2*>(g_xh)[i * 2 + 1] = __floats2half2_rn(v.z, v.w);
    }
    if (i < EE) {        // histogram + rank
        int r = atomicAdd(&g_cnt[dst[i]], 1);
        g_rank[i] = (uint16_t)r;
    }
    if (i < 65536) {     // weight concat
        int l   = i >> 15;
        int rem = i & 32767;     // f*256 + k
        int f   = rem >> 8;
        int k   = rem & 255;
        const float* W = l ? (k < 128 ? Ws2 : Wn2) : (k < 128 ? Ws1 : Wn1);
        g_wcat[l][rem] = __float2half_rn(W[f * 128 + (k & 127)]);
    }
    if (i < SCAN_BLOCKS) g_state[i] = 0ULL;   // reset lookback state for k_scan
}

// ---------------------------------------------------------------------------
// decoupled-lookback scan over g_cnt -> g_rowstart; re-zeroes g_cnt for the
// next graph replay (same-thread read-then-write).
// ---------------------------------------------------------------------------
__global__ void k_scan() {
    __shared__ int sm[256];
    __shared__ int s_prefix;
    const int b = blockIdx.x;
    const int t = threadIdx.x;
    const int i = b * 256 + t;

    int v = (i < NN) ? g_cnt[i] : 0;
    if (i < NN) g_cnt[i] = 0;        // restore zero state for next replay
    sm[t] = v;
    __syncthreads();
#pragma unroll
    for (int ofs = 1; ofs < 256; ofs <<= 1) {
        int tv = (t >= ofs) ? sm[t - ofs] : 0;
        __syncthreads();
        sm[t] += tv;
        __syncthreads();
    }
    int incl  = sm[t];
    int total = sm[255];

    if (t == 0) {
        if (b == 0) {
            atomicExch(&g_state[0], (2ULL << 32) | (unsigned)total);
            s_prefix = 0;
        } else {
            atomicExch(&g_state[b], (1ULL << 32) | (unsigned)total);
            int run = 0;
            for (int p = b - 1; p >= 0; p--) {
                unsigned long long s;
                do { s = atomicAdd(&g_state[p], 0ULL); } while ((s >> 32) == 0ULL);
                run += (int)(unsigned)s;
                if ((s >> 32) == 2ULL) break;
            }
            s_prefix = run;
            atomicExch(&g_state[b], (2ULL << 32) | (unsigned)(run + total));
        }
    }
    __syncthreads();

    if (i < NN) g_rowstart[i] = s_prefix + incl - v;
    if (i == 0) g_rowstart[NN] = EE;
}

// ---------------------------------------------------------------------------
// fill (atomic-free): pos = rowstart[dst] + rank; decode-free 8B entries
// ---------------------------------------------------------------------------
__global__ void k_fill(const int* __restrict__ src,
                       const int* __restrict__ dst,
                       const float* __restrict__ w) {
    int e = blockIdx.x * blockDim.x + threadIdx.x;
    if (e >= EE) return;
    int pos = g_rowstart[dst[e]] + (int)g_rank[e];
    g_el2[pos] = make_uint2((unsigned)src[e] * 32u, __float_as_uint(w[e]));
}

// ---------------------------------------------------------------------------
// Gather-aggregate over fp16 features (exact R12 shape — measured optimum):
// one warp per dst node, lane l owns 4 consecutive features (8 bytes),
// decode-free edge entries, straight 4x unroll, fp32 accumulation,
// fp16 output (the store IS the rounding).
// ---------------------------------------------------------------------------
__global__ void k_gather(const __half* __restrict__ h,
                         __half* __restrict__ neigh) {
    const int n = (blockIdx.x * blockDim.x + threadIdx.x) >> 5;
    if (n >= NN) return;
    const int lane = threadIdx.x & 31;

    const int start = g_rowstart[n];
    const int end   = g_rowstart[n + 1];
    const uint2* h2 = reinterpret_cast<const uint2*>(h);  // 8B = 4 halves

    float a0 = 0.f, a1 = 0.f, a2 = 0.f, a3 = 0.f;

    auto accum = [&](uint2 e) {
        float w = __uint_as_float(e.y);
        uint2 raw = h2[(size_t)e.x + lane];
        __half2 p0 = *reinterpret_cast<__half2*>(&raw.x);
        __half2 p1 = *reinterpret_cast<__half2*>(&raw.y);
        float2 f0 = __half22float2(p0);
        float2 f1 = __half22float2(p1);
        a0 = fmaf(w, f0.x, a0);
        a1 = fmaf(w, f0.y, a1);
        a2 = fmaf(w, f1.x, a2);
        a3 = fmaf(w, f1.y, a3);
    };

    int i = start;
    for (; i + 3 < end; i += 4) {
        uint2 e0 = g_el2[i];
        uint2 e1 = g_el2[i + 1];
        uint2 e2 = g_el2[i + 2];
        uint2 e3 = g_el2[i + 3];
        accum(e0); accum(e1); accum(e2); accum(e3);
    }
    for (; i < end; i++) accum(g_el2[i]);

    int deg = end - start;
    float inv = 1.0f / (float)max(deg, 1);
    __half2 r0 = __floats2half2_rn(a0 * inv, a1 * inv);
    __half2 r1 = __floats2half2_rn(a2 * inv, a3 * inv);
    uint2 packed;
    packed.x = *reinterpret_cast<unsigned*>(&r0);
    packed.y = *reinterpret_cast<unsigned*>(&r1);
    reinterpret_cast<uint2*>(neigh)[(size_t)n * 32 + lane] = packed;
}

// ---------------------------------------------------------------------------
// Persistent fused SAGE GEMM, fp16 mma.sync.m16n8k16, fp32 accumulate.
// 296 CTAs (2/SM) loop over 782 M-tiles. B staged once per CTA; A double-
// buffered via cp.async; one barrier per chunk. (R14 — measured at the
// legacy-HMMA rate ceiling.)
// ---------------------------------------------------------------------------
#define SWZ(r, w) (((r) << 5) + ((w) ^ (((r) & 7) << 2)))

template <bool RELU, bool OUT_HALF>
__global__ void __launch_bounds__(256, 2)
k_gemm_fp16(const __half* __restrict__ X,
            const __half* __restrict__ S,
            const __half* __restrict__ Wcat,   // [128][256] fp16
            const float* __restrict__ bias,
            float* __restrict__ out,
            __half* __restrict__ outh) {
    extern __shared__ unsigned dsm[];
    unsigned* Asm = dsm;           // [2][4096] words
    unsigned* Bsm = dsm + 8192;    // [4][4096] words

    const int tid  = threadIdx.x;
    const int wid  = tid >> 5;
    const int lane = tid & 31;
    const int wm   = (wid & 1) * 64;
    const int wn   = (wid >> 1) * 32;
    const int gr   = lane >> 2;
    const int gc   = lane & 3;

    int rr[4], cc8[4];
#pragma unroll
    for (int l = 0; l < 4; l++) {
        int idx = l * 256 + tid;
        rr[l]  = idx >> 3;
        cc8[l] = idx & 7;
    }

    // --- stage ALL of B once (64 KB, 16 cp16 per thread)
#pragma unroll
    for (int c = 0; c < 4; c++) {
#pragma unroll
        for (int l = 0; l < 4; l++) {
            cp16(&Bsm[c * 4096 + SWZ(rr[l], cc8[l] * 4)],
                 Wcat + (size_t)rr[l] * 256 + c * 64 + cc8[l] * 8, true);
        }
    }
    cp_commit();
    cp_wait0();
    __syncthreads();

    auto issueA = [&](int c, int buf, int bm0) {
        const __half* base = (c < 2) ? X : S;
        const int kb = (c & 1) * 64;
#pragma unroll
        for (int l = 0; l < 4; l++) {
            int grow = bm0 + rr[l];
            bool p = grow < NN;
            int gsafe = p ? grow : 0;
            const __half* gp = base + (size_t)gsafe * 128 + kb + cc8[l] * 8;
            cp16(&Asm[buf * 4096 + SWZ(rr[l], cc8[l] * 4)], gp, p);
        }
        cp_commit();
    };

    for (int tile = blockIdx.x; tile < GEMM_TILES; tile += gridDim.x) {
        const int bm0 = tile * 128;

        float acc[4][4][4];
#pragma unroll
        for (int mi = 0; mi < 4; mi++)
#pragma unroll
            for (int ni = 0; ni < 4; ni++)
#pragma unroll
                for (int c = 0; c < 4; c++) acc[mi][ni][c] = 0.f;

        issueA(0, 0, bm0);

#pragma unroll 1
        for (int c = 0; c < 4; c++) {
            cp_wait0();
            __syncthreads();          // chunk c staged; all warps done mma(c-1)

            if (c < 3) issueA(c + 1, (c + 1) & 1, bm0);   // overlaps mma below

            const unsigned* Ab = &Asm[(c & 1) * 4096];
            const unsigned* Bb = &Bsm[c * 4096];
#pragma unroll
            for (int ks = 0; ks < 4; ks++) {
                const int w0 = ks * 8;

                unsigned a[4][4];
#pragma unroll
                for (int mi = 0; mi < 4; mi++) {
                    int r = wm + mi * 16 + gr;
                    a[mi][0] = Ab[SWZ(r,     w0 + gc)];
                    a[mi][1] = Ab[SWZ(r + 8, w0 + gc)];
                    a[mi][2] = Ab[SWZ(r,     w0 + gc + 4)];
                    a[mi][3] = Ab[SWZ(r + 8, w0 + gc + 4)];
                }

                unsigned b[4][2];
#pragma unroll
                for (int ni = 0; ni < 4; ni++) {
                    int n = wn + ni * 8 + gr;
                    b[ni][0] = Bb[SWZ(n, w0 + gc)];
                    b[ni][1] = Bb[SWZ(n, w0 + gc + 4)];
                }

#pragma unroll
                for (int mi = 0; mi < 4; mi++)
#pragma unroll
                    for (int ni = 0; ni < 4; ni++)
                        mma_fp16(acc[mi][ni], a[mi], b[ni]);
            }
        }

        // --- epilogue: +bias, optional relu; fp16 or fp32 stores
#pragma unroll
        for (int ni = 0; ni < 4; ni++) {
            int col = wn + ni * 8 + gc * 2;
            float b0 = bias[col];
            float b1 = bias[col + 1];
#pragma unroll
            for (int mi = 0; mi < 4; mi++) {
                int r0 = bm0 + wm + mi * 16 + gr;
                float2 v0, v1;
                v0.x = acc[mi][ni][0] + b0;
                v0.y = acc[mi][ni][1] + b1;
                v1.x = acc[mi][ni][2] + b0;
                v1.y = acc[mi][ni][3] + b1;
                if (RELU) {
                    v0.x = fmaxf(v0.x, 0.f); v0.y = fmaxf(v0.y, 0.f);
                    v1.x = fmaxf(v1.x, 0.f); v1.y = fmaxf(v1.y, 0.f);
                }
                if (r0 < NN) {
                    if (OUT_HALF)
                        *reinterpret_cast<__half2*>(&outh[(size_t)r0 * 128 + col]) =
                            __floats2half2_rn(v0.x, v0.y);
                    else
                        *reinterpret_cast<float2*>(&out[(size_t)r0 * 128 + col]) = v0;
                }
                if (r0 + 8 < NN) {
                    if (OUT_HALF)
                        *reinterpret_cast<__half2*>(&outh[(size_t)(r0 + 8) * 128 + col]) =
                            __floats2half2_rn(v1.x, v1.y);
                    else
                        *reinterpret_cast<float2*>(&out[(size_t)(r0 + 8) * 128 + col]) = v1;
                }
            }
        }
    }
}

// ---------------------------------------------------------------------------
// launch  (7 graph nodes, no memsets; gather1 is kernel #4 -> ncu slot)
// ---------------------------------------------------------------------------
extern "C" void kernel_launch(void* const* d_in, const int* in_sizes, int n_in,
                              void* d_out, int out_size) {
    const float* in_feat = (const float*)d_in[0];
    const float* weights = (const float*)d_in[1];
    const int*   src     = (const int*)d_in[2];
    const int*   dst     = (const int*)d_in[3];
    const float* Ws1     = (const float*)d_in[4];
    const float* b1      = (const float*)d_in[5];
    const float* Wn1     = (const float*)d_in[6];
    const float* Ws2     = (const float*)d_in[7];
    const float* b2      = (const float*)d_in[8];
    const float* Wn2     = (const float*)d_in[9];
    float* out = (float*)d_out;

    void *p_xh, *p_hh, *p_sh, *p_w;
    cudaGetSymbolAddress(&p_xh, g_xh);
    cudaGetSymbolAddress(&p_hh, g_hh);
    cudaGetSymbolAddress(&p_sh, g_sh);
    cudaGetSymbolAddress(&p_w, g_wcat);
    __half* xh = (__half*)p_xh;
    __half* hh = (__half*)p_hh;
    __half* sh = (__half*)p_sh;
    __half* w0 = (__half*)p_w;
    __half* w1 = w0 + 128 * 256;

    cudaFuncSetAttribute(k_gemm_fp16<true, true>,
                         cudaFuncAttributeMaxDynamicSharedMemorySize, GEMM_SMEM);
    cudaFuncSetAttribute(k_gemm_fp16<false, false>,
                         cudaFuncAttributeMaxDynamicSharedMemorySize, GEMM_SMEM);

    const int eb = (EE + 255) / 256;
    const int big_blocks = (NN * 32 + 255) / 256;     // 12500

    k_prephist<<<big_blocks, 256>>>(in_feat, dst, Ws1, Wn1, Ws2, Wn2);  // 1
    k_scan<<<SCAN_BLOCKS, 256>>>();                                     // 2
    k_fill<<<eb, 256>>>(src, dst, weights);                             // 3

    // Layer 1
    k_gather<<<big_blocks, 256>>>(xh, sh);                              // 4 (profiled)
    k_gemm_fp16<true, true><<<GEMM_CTAS, 256, GEMM_SMEM>>>(             // 5
        xh, sh, w0, b1, nullptr, hh);

    // Layer 2
    k_gather<<<big_blocks, 256>>>(hh, sh);                              // 6
    k_gemm_fp16<false, false><<<GEMM_CTAS, 256, GEMM_SMEM>>>(           // 7
        hh, sh, w1, b2, out, nullptr);
}